// round 14
// baseline (speedup 1.0000x reference)
#include <cuda_runtime.h>
#include <cuda_bf16.h>
#include <mma.h>
#include <stdint.h>

using namespace nvcuda;

#define N_TOK 32768
#define DIM   512
#define KCB   1024

#define DECAY 0.99f
#define OMD   0.01f
#define EPS_C 1e-5f
#define MARGIN 0.15f   // ~40 sigma of bf16 score error
#define SLOTS 10

// ---------------- scratch (no allocations allowed) ----------------
__device__ float g_c2[KCB];
__device__ float g_z2[N_TOK];
__device__ int   g_idx[N_TOK];
__device__ float g_counts[KCB];
__device__ float g_sums[KCB * DIM];
__device__ float g_newcs[KCB];
__device__ float g_ntot;
__device__ float g_norm[KCB * DIM];
__device__ __align__(16) __nv_bfloat16 g_zh[N_TOK * (size_t)DIM];
__device__ __align__(16) __nv_bfloat16 g_cbh[KCB * DIM];
__device__ float g_scores[(size_t)KCB * N_TOK];   // [code][row]

// ---------------- zero accumulators ----------------
__global__ void zero_kernel() {
    int t = blockIdx.x * blockDim.x + threadIdx.x;
    int stride = gridDim.x * blockDim.x;
    for (int i = t; i < KCB * DIM; i += stride) g_sums[i] = 0.0f;
    if (t < KCB) g_counts[t] = 0.0f;
}

// ---------------- c2/z2 + fused bf16 conversion ----------------
__global__ void c2_kernel(const float* __restrict__ cb) {
    int k = blockIdx.x, t = threadIdx.x;  // 128 threads
    float4 v = ((const float4*)(cb + (size_t)k * DIM))[t];
    union { __nv_bfloat162 h[2]; uint2 u; } cv;
    cv.h[0] = __floats2bfloat162_rn(v.x, v.y);
    cv.h[1] = __floats2bfloat162_rn(v.z, v.w);
    ((uint2*)(g_cbh + (size_t)k * DIM))[t] = cv.u;
    float s = v.x * v.x + v.y * v.y + v.z * v.z + v.w * v.w;
    #pragma unroll
    for (int o = 16; o > 0; o >>= 1) s += __shfl_down_sync(0xffffffffu, s, o);
    __shared__ float ws[4];
    if ((t & 31) == 0) ws[t >> 5] = s;
    __syncthreads();
    if (t == 0) g_c2[k] = ws[0] + ws[1] + ws[2] + ws[3];
}

__global__ void z2_kernel(const float* __restrict__ z) {
    int r = blockIdx.x, t = threadIdx.x;  // 128 threads
    float4 v = ((const float4*)(z + (size_t)r * DIM))[t];
    union { __nv_bfloat162 h[2]; uint2 u; } cv;
    cv.h[0] = __floats2bfloat162_rn(v.x, v.y);
    cv.h[1] = __floats2bfloat162_rn(v.z, v.w);
    ((uint2*)(g_zh + (size_t)r * DIM))[t] = cv.u;
    float s = v.x * v.x + v.y * v.y + v.z * v.z + v.w * v.w;
    #pragma unroll
    for (int o = 16; o > 0; o >>= 1) s += __shfl_down_sync(0xffffffffu, s, o);
    __shared__ float ws[4];
    if ((t & 31) == 0) ws[t >> 5] = s;
    __syncthreads();
    if (t == 0) g_z2[r] = ws[0] + ws[1] + ws[2] + ws[3];
}

// ---------------- HMMA (wmma bf16) candidate GEMM ----------------
// VERBATIM R11 kernel (measured 239.6us, tensor=23.6%). Scores -> global.
#define PAW 72     // A/B smem pitch in bf16 (64 data + 8 pad)
#define PCW 132    // C smem pitch in f32 (128 rows + 4 pad)
#define OFF_A 0
#define OFF_B 18432
#define OFF_C 36864
#define OFF_C2 104448
#define GSM_SIZE 104960

__global__ __launch_bounds__(256)
void gemm_kernel() {
    extern __shared__ __align__(16) unsigned char sm[];
    __nv_bfloat16* As = (__nv_bfloat16*)(sm + OFF_A);   // [128][PAW]
    __nv_bfloat16* Bs = (__nv_bfloat16*)(sm + OFF_B);   // [128][PAW]
    float* Cs  = (float*)(sm + OFF_C);                  // [128 codes][PCW]
    float* c2s = (float*)(sm + OFF_C2);                 // [128]

    const int tid = threadIdx.x;
    const int wid = tid >> 5;
    const int wr = wid & 3;    // row group: rows wr*32
    const int wc = wid >> 2;   // col group: codes wc*64
    const int rb = blockIdx.x * 128;

    wmma::fragment<wmma::matrix_a, 16, 16, 16, __nv_bfloat16, wmma::row_major> af[2];
    wmma::fragment<wmma::matrix_b, 16, 16, 16, __nv_bfloat16, wmma::col_major> bf[4];
    wmma::fragment<wmma::accumulator, 16, 16, 16, float> acc[2][4];

    for (int ch = 0; ch < 8; ch++) {
        if (tid < 128) c2s[tid] = g_c2[ch * 128 + tid];
        #pragma unroll
        for (int f = 0; f < 2; f++)
            #pragma unroll
            for (int g = 0; g < 4; g++)
                wmma::fill_fragment(acc[f][g], 0.0f);

        for (int slab = 0; slab < 8; slab++) {
            #pragma unroll
            for (int i = 0; i < 4; i++) {
                int idx = i * 256 + tid;           // 0..1023
                int r = idx >> 3, grp = idx & 7;
                *(uint4*)(As + r * PAW + grp * 8) =
                    *(const uint4*)(g_zh + (size_t)(rb + r) * DIM + slab * 64 + grp * 8);
            }
            #pragma unroll
            for (int i = 0; i < 4; i++) {
                int idx = i * 256 + tid;
                int n = idx >> 3, grp = idx & 7;
                *(uint4*)(Bs + n * PAW + grp * 8) =
                    *(const uint4*)(g_cbh + (size_t)(ch * 128 + n) * DIM + slab * 64 + grp * 8);
            }
            __syncthreads();

            #pragma unroll
            for (int ks = 0; ks < 4; ks++) {
                #pragma unroll
                for (int f = 0; f < 2; f++)
                    wmma::load_matrix_sync(af[f],
                        As + (wr * 32 + f * 16) * PAW + ks * 16, PAW);
                #pragma unroll
                for (int g = 0; g < 4; g++)
                    wmma::load_matrix_sync(bf[g],
                        Bs + (wc * 64 + g * 16) * PAW + ks * 16, PAW);
                #pragma unroll
                for (int f = 0; f < 2; f++)
                    #pragma unroll
                    for (int g = 0; g < 4; g++)
                        wmma::mma_sync(acc[f][g], af[f], bf[g], acc[f][g]);
            }
            __syncthreads();
        }

        // store acc col-major: element (row r, code c) -> Cs[c*PCW + r]
        #pragma unroll
        for (int f = 0; f < 2; f++)
            #pragma unroll
            for (int g = 0; g < 4; g++)
                wmma::store_matrix_sync(
                    Cs + (wc * 64 + g * 16) * PCW + wr * 32 + f * 16,
                    acc[f][g], PCW, wmma::mem_col_major);
        __syncthreads();

        // coalesced transposed write: score = c2 - 2*dot
        #pragma unroll
        for (int i = 0; i < 64; i++) {
            int idx = i * 256 + tid;
            int r = idx & 127;
            int c = idx >> 7;
            float dot = Cs[c * PCW + r];
            g_scores[(size_t)(ch * 128 + c) * N_TOK + rb + r] =
                fmaf(-2.0f, dot, c2s[c]);
        }
        __syncthreads();
    }
}

// ---------------- single-pass scan + exact fp32 rerank ----------------
// Block = 256 consecutive rows, thread owns one row. Coalesced stream over
// codes; running min + superset candidate collection (provisional threshold
// >= final threshold -> no true candidate missed; final filter after).
// Rerank: exact reference arithmetic (sequential ascending-d fp32 FMA
// chain, fl(fl(z2-2dot)+c2), ascending-code order + strict '<' = lowest-
// index tie-break) — identical decision rule to the R4/R7/R11 passing
// kernels.
__global__ __launch_bounds__(256)
void scan_rerank_kernel(const float* __restrict__ z, const float* __restrict__ cb) {
    __shared__ int   s_cc[256][SLOTS];
    __shared__ float s_cs[256][SLOTS];
    const int tid = threadIdx.x;
    const int row = blockIdx.x * 256 + tid;

    float rm = 3.4e38f;
    int cnt = 0;
    const float* sp = g_scores + row;
    #pragma unroll 8
    for (int c = 0; c < KCB; c++) {
        float sc = sp[(size_t)c * N_TOK];
        rm = fminf(rm, sc);
        if (sc <= rm + MARGIN) {            // provisional threshold: superset
            if (cnt < SLOTS) { s_cc[tid][cnt] = c; s_cs[tid][cnt] = sc; }
            cnt++;
        }
    }

    const float thr = rm + MARGIN;          // final threshold
    const float z2v = g_z2[row];
    const float* zr = z + (size_t)row * DIM;
    float best = 3.4e38f;
    int bi = 0;
    if (cnt <= SLOTS) {
        for (int i = 0; i < cnt; i++) {
            if (s_cs[tid][i] > thr) continue;
            int code = s_cc[tid][i];
            const float* cr = cb + (size_t)code * DIM;
            float dot = 0.0f;
            #pragma unroll 8
            for (int d = 0; d < DIM; d++) dot = fmaf(zr[d], cr[d], dot);
            float t = fmaf(-2.0f, dot, z2v);
            float sc = __fadd_rn(t, g_c2[code]);
            if (sc < best) { best = sc; bi = code; }
        }
    } else {  // overflow fallback (prob ~0): per-thread exact full scan
        for (int code = 0; code < KCB; code++) {
            const float* cr = cb + (size_t)code * DIM;
            float dot = 0.0f;
            #pragma unroll 8
            for (int d = 0; d < DIM; d++) dot = fmaf(zr[d], cr[d], dot);
            float t = fmaf(-2.0f, dot, z2v);
            float sc = __fadd_rn(t, g_c2[code]);
            if (sc < best) { best = sc; bi = code; }
        }
    }
    g_idx[row] = bi;
}

// ---------------- scatter: counts[k] += 1, sums[k] += z_n ----------------
__global__ void scatter_kernel(const float* __restrict__ z) {
    int g = blockIdx.x * blockDim.x + threadIdx.x;
    int row = g >> 5;
    int lane = g & 31;
    if (row >= N_TOK) return;
    int k = g_idx[row];
    const float4* zr = (const float4*)(z + (size_t)row * DIM);
    float* dst = g_sums + (size_t)k * DIM;
    #pragma unroll
    for (int i = 0; i < 4; i++) {
        int e = lane + i * 32;
        float4 v = zr[e];
        atomicAdd(dst + 4 * e + 0, v.x);
        atomicAdd(dst + 4 * e + 1, v.y);
        atomicAdd(dst + 4 * e + 2, v.z);
        atomicAdd(dst + 4 * e + 3, v.w);
    }
    if (lane == 0) atomicAdd(&g_counts[k], 1.0f);
}

// ---------------- EMA cluster sizes + total n ----------------
__global__ void newcs_kernel(const float* __restrict__ ema_cs) {
    __shared__ float red[1024];
    int t = threadIdx.x;  // 1024 threads
    float v = DECAY * ema_cs[t] + OMD * g_counts[t];
    g_newcs[t] = v;
    red[t] = v;
    __syncthreads();
    for (int s = 512; s > 0; s >>= 1) {
        if (t < s) red[t] += red[t + s];
        __syncthreads();
    }
    if (t == 0) g_ntot = red[0];
}

// ---------------- normalized codebook ----------------
__global__ void norm_kernel(const float* __restrict__ ema_w) {
    int k = blockIdx.x;
    int t = threadIdx.x;  // 128 threads
    float n = g_ntot;
    float cs = g_newcs[k];
    float smoothed = (cs + EPS_C) / (n + (float)KCB * EPS_C) * n;
    float inv = 1.0f / smoothed;
    const float4* w = (const float4*)(ema_w + (size_t)k * DIM);
    const float4* s = (const float4*)(g_sums + (size_t)k * DIM);
    float4* o = (float4*)(g_norm + (size_t)k * DIM);
    float4 wv = w[t], sv = s[t], ov;
    ov.x = (DECAY * wv.x + OMD * sv.x) * inv;
    ov.y = (DECAY * wv.y + OMD * sv.y) * inv;
    ov.z = (DECAY * wv.z + OMD * sv.z) * inv;
    ov.w = (DECAY * wv.w + OMD * sv.w) * inv;
    o[t] = ov;
}

// ---------------- gather + emit outputs ----------------
__global__ void out_kernel(const float* __restrict__ z,
                           float* __restrict__ idx_out,
                           float* __restrict__ q_out,
                           float* __restrict__ st_out) {
    int row = blockIdx.x;
    int t = threadIdx.x;  // 128 threads
    int k = g_idx[row];
    const float4* nr = (const float4*)(g_norm + (size_t)k * DIM);
    float4 qv = nr[t];
    if (q_out)
        ((float4*)(q_out + (size_t)row * DIM))[t] = qv;
    if (st_out) {
        const float4* zr = (const float4*)(z + (size_t)row * DIM);
        float4 zv = zr[t];
        float4 sv;
        sv.x = zv.x + (qv.x - zv.x);
        sv.y = zv.y + (qv.y - zv.y);
        sv.z = zv.z + (qv.z - zv.z);
        sv.w = zv.w + (qv.w - zv.w);
        ((float4*)(st_out + (size_t)row * DIM))[t] = sv;
    }
    if (idx_out && t == 0) idx_out[row] = (float)k;
}

// ---------------- host launcher ----------------
extern "C" void kernel_launch(void* const* d_in, const int* in_sizes, int n_in,
                              void* d_out, int out_size) {
    const float* z   = (const float*)d_in[0];
    const float* cb  = (const float*)d_in[1];
    const float* ecs = (const float*)d_in[2];
    const float* ew  = (const float*)d_in[3];
    float* out = (float*)d_out;

    static bool attr_set = false;
    if (!attr_set) {
        cudaFuncSetAttribute(gemm_kernel,
                             cudaFuncAttributeMaxDynamicSharedMemorySize,
                             GSM_SIZE);
        attr_set = true;
    }

    zero_kernel<<<512, 256>>>();
    c2_kernel<<<KCB, 128>>>(cb);
    z2_kernel<<<N_TOK, 128>>>(z);
    gemm_kernel<<<N_TOK / 128, 256, GSM_SIZE>>>();
    scan_rerank_kernel<<<N_TOK / 256, 256>>>(z, cb);
    scatter_kernel<<<(N_TOK * 32) / 256, 256>>>(z);
    newcs_kernel<<<1, 1024>>>(ecs);
    norm_kernel<<<KCB, 128>>>(ew);

    const long long N = N_TOK, D = DIM;
    const long long os = out_size;
    float *idxp = nullptr, *qp = nullptr, *stp = nullptr;
    if (os == N * (2 * D + 1)) {            // [idx, q, q_st]
        idxp = out; qp = out + N; stp = out + N + N * D;
    } else if (os == N * 2 * D) {           // [q, q_st]
        qp = out; stp = out + N * D;
    } else if (os == N * D) {               // [q]
        qp = out;
    } else if (os == N) {                   // [idx]
        idxp = out;
    } else {
        idxp = out;
        if (os >= N + N * D) qp = out + N;
        if (os >= N + 2 * N * D) stp = out + N + N * D;
    }
    out_kernel<<<N_TOK, 128>>>(z, idxp, qp, stp);
}

// round 15
// speedup vs baseline: 2.7657x; 2.7657x over previous
#include <cuda_runtime.h>
#include <cuda_bf16.h>
#include <mma.h>
#include <stdint.h>

using namespace nvcuda;

#define N_TOK 32768
#define DIM   512
#define KCB   1024

#define DECAY 0.99f
#define OMD   0.01f
#define EPS_C 1e-5f
#define MARGIN 0.15f   // ~40 sigma of bf16 score error
#define SLOTS 10

// ---------------- scratch (no allocations allowed) ----------------
__device__ float g_c2[KCB];
__device__ float g_z2[N_TOK];
__device__ int   g_idx[N_TOK];
__device__ float g_counts[KCB];
__device__ float g_sums[KCB * DIM];
__device__ float g_newcs[KCB];
__device__ float g_ntot;
__device__ float g_norm[KCB * DIM];
__device__ __align__(16) __nv_bfloat16 g_zh[N_TOK * (size_t)DIM];
__device__ __align__(16) __nv_bfloat16 g_cbh[KCB * DIM];
__device__ float g_scores[(size_t)KCB * N_TOK];   // [code][row]

// ---------------- zero accumulators ----------------
__global__ void zero_kernel() {
    int t = blockIdx.x * blockDim.x + threadIdx.x;
    int stride = gridDim.x * blockDim.x;
    for (int i = t; i < KCB * DIM; i += stride) g_sums[i] = 0.0f;
    if (t < KCB) g_counts[t] = 0.0f;
}

// ---------------- c2/z2 + fused bf16 conversion ----------------
__global__ void c2_kernel(const float* __restrict__ cb) {
    int k = blockIdx.x, t = threadIdx.x;  // 128 threads
    float4 v = ((const float4*)(cb + (size_t)k * DIM))[t];
    union { __nv_bfloat162 h[2]; uint2 u; } cv;
    cv.h[0] = __floats2bfloat162_rn(v.x, v.y);
    cv.h[1] = __floats2bfloat162_rn(v.z, v.w);
    ((uint2*)(g_cbh + (size_t)k * DIM))[t] = cv.u;
    float s = v.x * v.x + v.y * v.y + v.z * v.z + v.w * v.w;
    #pragma unroll
    for (int o = 16; o > 0; o >>= 1) s += __shfl_down_sync(0xffffffffu, s, o);
    __shared__ float ws[4];
    if ((t & 31) == 0) ws[t >> 5] = s;
    __syncthreads();
    if (t == 0) g_c2[k] = ws[0] + ws[1] + ws[2] + ws[3];
}

__global__ void z2_kernel(const float* __restrict__ z) {
    int r = blockIdx.x, t = threadIdx.x;  // 128 threads
    float4 v = ((const float4*)(z + (size_t)r * DIM))[t];
    union { __nv_bfloat162 h[2]; uint2 u; } cv;
    cv.h[0] = __floats2bfloat162_rn(v.x, v.y);
    cv.h[1] = __floats2bfloat162_rn(v.z, v.w);
    ((uint2*)(g_zh + (size_t)r * DIM))[t] = cv.u;
    float s = v.x * v.x + v.y * v.y + v.z * v.z + v.w * v.w;
    #pragma unroll
    for (int o = 16; o > 0; o >>= 1) s += __shfl_down_sync(0xffffffffu, s, o);
    __shared__ float ws[4];
    if ((t & 31) == 0) ws[t >> 5] = s;
    __syncthreads();
    if (t == 0) g_z2[r] = ws[0] + ws[1] + ws[2] + ws[3];
}

// ---------------- HMMA (wmma bf16) candidate GEMM ----------------
// VERBATIM R11 kernel (measured 239.6us, tensor=23.6%). Scores -> global.
#define PAW 72     // A/B smem pitch in bf16 (64 data + 8 pad)
#define PCW 132    // C smem pitch in f32 (128 rows + 4 pad)
#define OFF_A 0
#define OFF_B 18432
#define OFF_C 36864
#define OFF_C2 104448
#define GSM_SIZE 104960

__global__ __launch_bounds__(256)
void gemm_kernel() {
    extern __shared__ __align__(16) unsigned char sm[];
    __nv_bfloat16* As = (__nv_bfloat16*)(sm + OFF_A);   // [128][PAW]
    __nv_bfloat16* Bs = (__nv_bfloat16*)(sm + OFF_B);   // [128][PAW]
    float* Cs  = (float*)(sm + OFF_C);                  // [128 codes][PCW]
    float* c2s = (float*)(sm + OFF_C2);                 // [128]

    const int tid = threadIdx.x;
    const int wid = tid >> 5;
    const int wr = wid & 3;    // row group: rows wr*32
    const int wc = wid >> 2;   // col group: codes wc*64
    const int rb = blockIdx.x * 128;

    wmma::fragment<wmma::matrix_a, 16, 16, 16, __nv_bfloat16, wmma::row_major> af[2];
    wmma::fragment<wmma::matrix_b, 16, 16, 16, __nv_bfloat16, wmma::col_major> bf[4];
    wmma::fragment<wmma::accumulator, 16, 16, 16, float> acc[2][4];

    for (int ch = 0; ch < 8; ch++) {
        if (tid < 128) c2s[tid] = g_c2[ch * 128 + tid];
        #pragma unroll
        for (int f = 0; f < 2; f++)
            #pragma unroll
            for (int g = 0; g < 4; g++)
                wmma::fill_fragment(acc[f][g], 0.0f);

        for (int slab = 0; slab < 8; slab++) {
            #pragma unroll
            for (int i = 0; i < 4; i++) {
                int idx = i * 256 + tid;           // 0..1023
                int r = idx >> 3, grp = idx & 7;
                *(uint4*)(As + r * PAW + grp * 8) =
                    *(const uint4*)(g_zh + (size_t)(rb + r) * DIM + slab * 64 + grp * 8);
            }
            #pragma unroll
            for (int i = 0; i < 4; i++) {
                int idx = i * 256 + tid;
                int n = idx >> 3, grp = idx & 7;
                *(uint4*)(Bs + n * PAW + grp * 8) =
                    *(const uint4*)(g_cbh + (size_t)(ch * 128 + n) * DIM + slab * 64 + grp * 8);
            }
            __syncthreads();

            #pragma unroll
            for (int ks = 0; ks < 4; ks++) {
                #pragma unroll
                for (int f = 0; f < 2; f++)
                    wmma::load_matrix_sync(af[f],
                        As + (wr * 32 + f * 16) * PAW + ks * 16, PAW);
                #pragma unroll
                for (int g = 0; g < 4; g++)
                    wmma::load_matrix_sync(bf[g],
                        Bs + (wc * 64 + g * 16) * PAW + ks * 16, PAW);
                #pragma unroll
                for (int f = 0; f < 2; f++)
                    #pragma unroll
                    for (int g = 0; g < 4; g++)
                        wmma::mma_sync(acc[f][g], af[f], bf[g], acc[f][g]);
            }
            __syncthreads();
        }

        // store acc col-major: element (row r, code c) -> Cs[c*PCW + r]
        #pragma unroll
        for (int f = 0; f < 2; f++)
            #pragma unroll
            for (int g = 0; g < 4; g++)
                wmma::store_matrix_sync(
                    Cs + (wc * 64 + g * 16) * PCW + wr * 32 + f * 16,
                    acc[f][g], PCW, wmma::mem_col_major);
        __syncthreads();

        // coalesced transposed write: score = c2 - 2*dot
        #pragma unroll
        for (int i = 0; i < 64; i++) {
            int idx = i * 256 + tid;
            int r = idx & 127;
            int c = idx >> 7;
            float dot = Cs[c * PCW + r];
            g_scores[(size_t)(ch * 128 + c) * N_TOK + rb + r] =
                fmaf(-2.0f, dot, c2s[c]);
        }
        __syncthreads();
    }
}

// ---------------- two-pass scan + exact fp32 rerank ----------------
// Block = 256 consecutive rows, thread owns one row (coalesced streams).
// PASS 1: branch-free min-reduce (4 independent chains -> loads batched).
// PASS 2: collect candidates against the FINAL threshold rm+MARGIN
//   (expected ~1.3 candidates/row; SLOTS overflow prob ~0 — the R14
//   running-min collection overflowed for most rows and was the 35ms bug).
// Rerank: exact reference arithmetic (sequential ascending-d fp32 FMA
// chain, fl(fl(z2-2dot)+c2), ascending-code order + strict '<' = lowest-
// index tie-break) — identical decision rule to the R4/R7/R11 passing
// kernels.
__global__ __launch_bounds__(256)
void scan_rerank_kernel(const float* __restrict__ z, const float* __restrict__ cb) {
    const int tid = threadIdx.x;
    const int row = blockIdx.x * 256 + tid;
    const float* sp = g_scores + row;

    // pass 1: pure min, 4 chains
    float m0 = 3.4e38f, m1 = 3.4e38f, m2 = 3.4e38f, m3 = 3.4e38f;
    #pragma unroll 2
    for (int c = 0; c < KCB; c += 8) {
        m0 = fminf(m0, fminf(sp[(size_t)(c + 0) * N_TOK], sp[(size_t)(c + 4) * N_TOK]));
        m1 = fminf(m1, fminf(sp[(size_t)(c + 1) * N_TOK], sp[(size_t)(c + 5) * N_TOK]));
        m2 = fminf(m2, fminf(sp[(size_t)(c + 2) * N_TOK], sp[(size_t)(c + 6) * N_TOK]));
        m3 = fminf(m3, fminf(sp[(size_t)(c + 3) * N_TOK], sp[(size_t)(c + 7) * N_TOK]));
    }
    const float rm = fminf(fminf(m0, m1), fminf(m2, m3));
    const float thr = rm + MARGIN;   // FINAL threshold

    // pass 2: collect (branch almost never taken)
    int cand[SLOTS];
    int cnt = 0;
    #pragma unroll 4
    for (int c = 0; c < KCB; c++) {
        float sc = sp[(size_t)c * N_TOK];
        if (sc <= thr) { if (cnt < SLOTS) cand[cnt] = c; cnt++; }
    }

    // exact rerank
    const float z2v = g_z2[row];
    const float* zr = z + (size_t)row * DIM;
    float best = 3.4e38f;
    int bi = 0;
    if (cnt <= SLOTS) {
        for (int i = 0; i < cnt; i++) {
            int code = cand[i];
            const float* cr = cb + (size_t)code * DIM;
            float dot = 0.0f;
            #pragma unroll 8
            for (int d = 0; d < DIM; d++) dot = fmaf(zr[d], cr[d], dot);
            float t = fmaf(-2.0f, dot, z2v);
            float sc = __fadd_rn(t, g_c2[code]);
            if (sc < best) { best = sc; bi = code; }
        }
    } else {  // overflow fallback (prob ~0): per-thread exact full scan
        for (int code = 0; code < KCB; code++) {
            const float* cr = cb + (size_t)code * DIM;
            float dot = 0.0f;
            #pragma unroll 8
            for (int d = 0; d < DIM; d++) dot = fmaf(zr[d], cr[d], dot);
            float t = fmaf(-2.0f, dot, z2v);
            float sc = __fadd_rn(t, g_c2[code]);
            if (sc < best) { best = sc; bi = code; }
        }
    }
    g_idx[row] = bi;
}

// ---------------- scatter: counts[k] += 1, sums[k] += z_n ----------------
__global__ void scatter_kernel(const float* __restrict__ z) {
    int g = blockIdx.x * blockDim.x + threadIdx.x;
    int row = g >> 5;
    int lane = g & 31;
    if (row >= N_TOK) return;
    int k = g_idx[row];
    const float4* zr = (const float4*)(z + (size_t)row * DIM);
    float* dst = g_sums + (size_t)k * DIM;
    #pragma unroll
    for (int i = 0; i < 4; i++) {
        int e = lane + i * 32;
        float4 v = zr[e];
        atomicAdd(dst + 4 * e + 0, v.x);
        atomicAdd(dst + 4 * e + 1, v.y);
        atomicAdd(dst + 4 * e + 2, v.z);
        atomicAdd(dst + 4 * e + 3, v.w);
    }
    if (lane == 0) atomicAdd(&g_counts[k], 1.0f);
}

// ---------------- EMA cluster sizes + total n ----------------
__global__ void newcs_kernel(const float* __restrict__ ema_cs) {
    __shared__ float red[1024];
    int t = threadIdx.x;  // 1024 threads
    float v = DECAY * ema_cs[t] + OMD * g_counts[t];
    g_newcs[t] = v;
    red[t] = v;
    __syncthreads();
    for (int s = 512; s > 0; s >>= 1) {
        if (t < s) red[t] += red[t + s];
        __syncthreads();
    }
    if (t == 0) g_ntot = red[0];
}

// ---------------- normalized codebook ----------------
__global__ void norm_kernel(const float* __restrict__ ema_w) {
    int k = blockIdx.x;
    int t = threadIdx.x;  // 128 threads
    float n = g_ntot;
    float cs = g_newcs[k];
    float smoothed = (cs + EPS_C) / (n + (float)KCB * EPS_C) * n;
    float inv = 1.0f / smoothed;
    const float4* w = (const float4*)(ema_w + (size_t)k * DIM);
    const float4* s = (const float4*)(g_sums + (size_t)k * DIM);
    float4* o = (float4*)(g_norm + (size_t)k * DIM);
    float4 wv = w[t], sv = s[t], ov;
    ov.x = (DECAY * wv.x + OMD * sv.x) * inv;
    ov.y = (DECAY * wv.y + OMD * sv.y) * inv;
    ov.z = (DECAY * wv.z + OMD * sv.z) * inv;
    ov.w = (DECAY * wv.w + OMD * sv.w) * inv;
    o[t] = ov;
}

// ---------------- gather + emit outputs ----------------
__global__ void out_kernel(const float* __restrict__ z,
                           float* __restrict__ idx_out,
                           float* __restrict__ q_out,
                           float* __restrict__ st_out) {
    int row = blockIdx.x;
    int t = threadIdx.x;  // 128 threads
    int k = g_idx[row];
    const float4* nr = (const float4*)(g_norm + (size_t)k * DIM);
    float4 qv = nr[t];
    if (q_out)
        ((float4*)(q_out + (size_t)row * DIM))[t] = qv;
    if (st_out) {
        const float4* zr = (const float4*)(z + (size_t)row * DIM);
        float4 zv = zr[t];
        float4 sv;
        sv.x = zv.x + (qv.x - zv.x);
        sv.y = zv.y + (qv.y - zv.y);
        sv.z = zv.z + (qv.z - zv.z);
        sv.w = zv.w + (qv.w - zv.w);
        ((float4*)(st_out + (size_t)row * DIM))[t] = sv;
    }
    if (idx_out && t == 0) idx_out[row] = (float)k;
}

// ---------------- host launcher ----------------
extern "C" void kernel_launch(void* const* d_in, const int* in_sizes, int n_in,
                              void* d_out, int out_size) {
    const float* z   = (const float*)d_in[0];
    const float* cb  = (const float*)d_in[1];
    const float* ecs = (const float*)d_in[2];
    const float* ew  = (const float*)d_in[3];
    float* out = (float*)d_out;

    static bool attr_set = false;
    if (!attr_set) {
        cudaFuncSetAttribute(gemm_kernel,
                             cudaFuncAttributeMaxDynamicSharedMemorySize,
                             GSM_SIZE);
        attr_set = true;
    }

    zero_kernel<<<512, 256>>>();
    c2_kernel<<<KCB, 128>>>(cb);
    z2_kernel<<<N_TOK, 128>>>(z);
    gemm_kernel<<<N_TOK / 128, 256, GSM_SIZE>>>();
    scan_rerank_kernel<<<N_TOK / 256, 256>>>(z, cb);
    scatter_kernel<<<(N_TOK * 32) / 256, 256>>>(z);
    newcs_kernel<<<1, 1024>>>(ecs);
    norm_kernel<<<KCB, 128>>>(ew);

    const long long N = N_TOK, D = DIM;
    const long long os = out_size;
    float *idxp = nullptr, *qp = nullptr, *stp = nullptr;
    if (os == N * (2 * D + 1)) {            // [idx, q, q_st]
        idxp = out; qp = out + N; stp = out + N + N * D;
    } else if (os == N * 2 * D) {           // [q, q_st]
        qp = out; stp = out + N * D;
    } else if (os == N * D) {               // [q]
        qp = out;
    } else if (os == N) {                   // [idx]
        idxp = out;
    } else {
        idxp = out;
        if (os >= N + N * D) qp = out + N;
        if (os >= N + 2 * N * D) stp = out + N + N * D;
    }
    out_kernel<<<N_TOK, 128>>>(z, idxp, qp, stp);
}

// round 16
// speedup vs baseline: 42.5265x; 15.3761x over previous
#include <cuda_runtime.h>
#include <cuda_bf16.h>
#include <mma.h>
#include <stdint.h>

using namespace nvcuda;

#define N_TOK 32768
#define DIM   512
#define KCB   1024

#define DECAY 0.99f
#define OMD   0.01f
#define EPS_C 1e-5f
#define MARGIN 0.15f   // candidate window; near-min spacing (Gumbel beta) ~0.22
#define SLOTS 16

// ---------------- scratch (no allocations allowed) ----------------
__device__ float g_c2[KCB];
__device__ float g_z2[N_TOK];
__device__ int   g_idx[N_TOK];
__device__ float g_counts[KCB];
__device__ float g_sums[KCB * DIM];
__device__ float g_newcs[KCB];
__device__ float g_ntot;
__device__ float g_norm[KCB * DIM];
__device__ __align__(16) __nv_bfloat16 g_zh[N_TOK * (size_t)DIM];
__device__ __align__(16) __nv_bfloat16 g_cbh[KCB * DIM];
__device__ float g_scores[(size_t)KCB * N_TOK];   // [code][row]

// ---------------- zero accumulators ----------------
__global__ void zero_kernel() {
    int t = blockIdx.x * blockDim.x + threadIdx.x;
    int stride = gridDim.x * blockDim.x;
    for (int i = t; i < KCB * DIM; i += stride) g_sums[i] = 0.0f;
    if (t < KCB) g_counts[t] = 0.0f;
}

// ---------------- c2/z2 + fused bf16 conversion ----------------
__global__ void c2_kernel(const float* __restrict__ cb) {
    int k = blockIdx.x, t = threadIdx.x;  // 128 threads
    float4 v = ((const float4*)(cb + (size_t)k * DIM))[t];
    union { __nv_bfloat162 h[2]; uint2 u; } cv;
    cv.h[0] = __floats2bfloat162_rn(v.x, v.y);
    cv.h[1] = __floats2bfloat162_rn(v.z, v.w);
    ((uint2*)(g_cbh + (size_t)k * DIM))[t] = cv.u;
    float s = v.x * v.x + v.y * v.y + v.z * v.z + v.w * v.w;
    #pragma unroll
    for (int o = 16; o > 0; o >>= 1) s += __shfl_down_sync(0xffffffffu, s, o);
    __shared__ float ws[4];
    if ((t & 31) == 0) ws[t >> 5] = s;
    __syncthreads();
    if (t == 0) g_c2[k] = ws[0] + ws[1] + ws[2] + ws[3];
}

__global__ void z2_kernel(const float* __restrict__ z) {
    int r = blockIdx.x, t = threadIdx.x;  // 128 threads
    float4 v = ((const float4*)(z + (size_t)r * DIM))[t];
    union { __nv_bfloat162 h[2]; uint2 u; } cv;
    cv.h[0] = __floats2bfloat162_rn(v.x, v.y);
    cv.h[1] = __floats2bfloat162_rn(v.z, v.w);
    ((uint2*)(g_zh + (size_t)r * DIM))[t] = cv.u;
    float s = v.x * v.x + v.y * v.y + v.z * v.z + v.w * v.w;
    #pragma unroll
    for (int o = 16; o > 0; o >>= 1) s += __shfl_down_sync(0xffffffffu, s, o);
    __shared__ float ws[4];
    if ((t & 31) == 0) ws[t >> 5] = s;
    __syncthreads();
    if (t == 0) g_z2[r] = ws[0] + ws[1] + ws[2] + ws[3];
}

// ---------------- HMMA (wmma bf16) candidate GEMM ----------------
// VERBATIM R11 kernel (measured 238.8us, tensor=23.8%). Scores -> global.
#define PAW 72     // A/B smem pitch in bf16 (64 data + 8 pad)
#define PCW 132    // C smem pitch in f32 (128 rows + 4 pad)
#define OFF_A 0
#define OFF_B 18432
#define OFF_C 36864
#define OFF_C2 104448
#define GSM_SIZE 104960

__global__ __launch_bounds__(256)
void gemm_kernel() {
    extern __shared__ __align__(16) unsigned char sm[];
    __nv_bfloat16* As = (__nv_bfloat16*)(sm + OFF_A);   // [128][PAW]
    __nv_bfloat16* Bs = (__nv_bfloat16*)(sm + OFF_B);   // [128][PAW]
    float* Cs  = (float*)(sm + OFF_C);                  // [128 codes][PCW]
    float* c2s = (float*)(sm + OFF_C2);                 // [128]

    const int tid = threadIdx.x;
    const int wid = tid >> 5;
    const int wr = wid & 3;    // row group: rows wr*32
    const int wc = wid >> 2;   // col group: codes wc*64
    const int rb = blockIdx.x * 128;

    wmma::fragment<wmma::matrix_a, 16, 16, 16, __nv_bfloat16, wmma::row_major> af[2];
    wmma::fragment<wmma::matrix_b, 16, 16, 16, __nv_bfloat16, wmma::col_major> bf[4];
    wmma::fragment<wmma::accumulator, 16, 16, 16, float> acc[2][4];

    for (int ch = 0; ch < 8; ch++) {
        if (tid < 128) c2s[tid] = g_c2[ch * 128 + tid];
        #pragma unroll
        for (int f = 0; f < 2; f++)
            #pragma unroll
            for (int g = 0; g < 4; g++)
                wmma::fill_fragment(acc[f][g], 0.0f);

        for (int slab = 0; slab < 8; slab++) {
            #pragma unroll
            for (int i = 0; i < 4; i++) {
                int idx = i * 256 + tid;           // 0..1023
                int r = idx >> 3, grp = idx & 7;
                *(uint4*)(As + r * PAW + grp * 8) =
                    *(const uint4*)(g_zh + (size_t)(rb + r) * DIM + slab * 64 + grp * 8);
            }
            #pragma unroll
            for (int i = 0; i < 4; i++) {
                int idx = i * 256 + tid;
                int n = idx >> 3, grp = idx & 7;
                *(uint4*)(Bs + n * PAW + grp * 8) =
                    *(const uint4*)(g_cbh + (size_t)(ch * 128 + n) * DIM + slab * 64 + grp * 8);
            }
            __syncthreads();

            #pragma unroll
            for (int ks = 0; ks < 4; ks++) {
                #pragma unroll
                for (int f = 0; f < 2; f++)
                    wmma::load_matrix_sync(af[f],
                        As + (wr * 32 + f * 16) * PAW + ks * 16, PAW);
                #pragma unroll
                for (int g = 0; g < 4; g++)
                    wmma::load_matrix_sync(bf[g],
                        Bs + (wc * 64 + g * 16) * PAW + ks * 16, PAW);
                #pragma unroll
                for (int f = 0; f < 2; f++)
                    #pragma unroll
                    for (int g = 0; g < 4; g++)
                        wmma::mma_sync(acc[f][g], af[f], bf[g], acc[f][g]);
            }
            __syncthreads();
        }

        // store acc col-major: element (row r, code c) -> Cs[c*PCW + r]
        #pragma unroll
        for (int f = 0; f < 2; f++)
            #pragma unroll
            for (int g = 0; g < 4; g++)
                wmma::store_matrix_sync(
                    Cs + (wc * 64 + g * 16) * PCW + wr * 32 + f * 16,
                    acc[f][g], PCW, wmma::mem_col_major);
        __syncthreads();

        // coalesced transposed write: score = c2 - 2*dot
        #pragma unroll
        for (int i = 0; i < 64; i++) {
            int idx = i * 256 + tid;
            int r = idx & 127;
            int c = idx >> 7;
            float dot = Cs[c * PCW + r];
            g_scores[(size_t)(ch * 128 + c) * N_TOK + rb + r] =
                fmaf(-2.0f, dot, c2s[c]);
        }
        __syncthreads();
    }
}

// ---------------- exact rescore of one candidate (reference-exact) -------
// Sequential ascending-d fp32 FMA chain; d2 = fl(fl(z2-2dot)+c2); callers
// process codes in ascending order with strict '<' => lowest-index tie-break.
// Identical decision arithmetic to the R4/R7/R11 passing kernels.
__device__ __forceinline__ void exact_update(const float* __restrict__ zr,
                                             const float* __restrict__ cb,
                                             float z2v, int code,
                                             float& best, int& bi) {
    const float* cr = cb + (size_t)code * DIM;
    float dot = 0.0f;
    #pragma unroll 8
    for (int d = 0; d < DIM; d++) dot = fmaf(zr[d], cr[d], dot);
    float t = fmaf(-2.0f, dot, z2v);
    float sc = __fadd_rn(t, g_c2[code]);
    if (sc < best) { best = sc; bi = code; }
}

// ---------------- two-pass scan + exact fp32 rerank ----------------
// Block = 256 consecutive rows, thread owns one row (coalesced streams).
// PASS 1: branch-free min-reduce. PASS 2: collect against the FINAL
// threshold rm+MARGIN (count ~geometric mean ~2; P(>16) ~ 1e-5/row).
// Overflow fallback is now CHUNKED: re-stream scores in ascending code
// order, refill the slot buffer, exact-rerank each chunk (cost ~0.1ms per
// overflow row vs the ~8ms full divergent scan that caused R14/R15's
// 35ms/13ms tails).
__global__ __launch_bounds__(256)
void scan_rerank_kernel(const float* __restrict__ z, const float* __restrict__ cb) {
    const int tid = threadIdx.x;
    const int row = blockIdx.x * 256 + tid;
    const float* sp = g_scores + row;

    // pass 1: pure min, 4 chains
    float m0 = 3.4e38f, m1 = 3.4e38f, m2 = 3.4e38f, m3 = 3.4e38f;
    #pragma unroll 2
    for (int c = 0; c < KCB; c += 8) {
        m0 = fminf(m0, fminf(sp[(size_t)(c + 0) * N_TOK], sp[(size_t)(c + 4) * N_TOK]));
        m1 = fminf(m1, fminf(sp[(size_t)(c + 1) * N_TOK], sp[(size_t)(c + 5) * N_TOK]));
        m2 = fminf(m2, fminf(sp[(size_t)(c + 2) * N_TOK], sp[(size_t)(c + 6) * N_TOK]));
        m3 = fminf(m3, fminf(sp[(size_t)(c + 3) * N_TOK], sp[(size_t)(c + 7) * N_TOK]));
    }
    const float rm = fminf(fminf(m0, m1), fminf(m2, m3));
    const float thr = rm + MARGIN;   // FINAL threshold

    // pass 2: collect (branch rarely taken)
    int cand[SLOTS];
    int cnt = 0;
    #pragma unroll 4
    for (int c = 0; c < KCB; c++) {
        float sc = sp[(size_t)c * N_TOK];
        if (sc <= thr) { if (cnt < SLOTS) cand[cnt] = c; cnt++; }
    }

    const float z2v = g_z2[row];
    const float* zr = z + (size_t)row * DIM;
    float best = 3.4e38f;
    int bi = 0;
    if (cnt <= SLOTS) {
        for (int i = 0; i < cnt; i++)
            exact_update(zr, cb, z2v, cand[i], best, bi);
    } else {
        // chunked fallback: ascending code order preserved across chunks
        int c = 0;
        while (c < KCB) {
            int n = 0;
            while (c < KCB && n < SLOTS) {
                float sc = sp[(size_t)c * N_TOK];
                if (sc <= thr) cand[n++] = c;
                c++;
            }
            for (int i = 0; i < n; i++)
                exact_update(zr, cb, z2v, cand[i], best, bi);
        }
    }
    g_idx[row] = bi;
}

// ---------------- scatter: counts[k] += 1, sums[k] += z_n ----------------
__global__ void scatter_kernel(const float* __restrict__ z) {
    int g = blockIdx.x * blockDim.x + threadIdx.x;
    int row = g >> 5;
    int lane = g & 31;
    if (row >= N_TOK) return;
    int k = g_idx[row];
    const float4* zr = (const float4*)(z + (size_t)row * DIM);
    float* dst = g_sums + (size_t)k * DIM;
    #pragma unroll
    for (int i = 0; i < 4; i++) {
        int e = lane + i * 32;
        float4 v = zr[e];
        atomicAdd(dst + 4 * e + 0, v.x);
        atomicAdd(dst + 4 * e + 1, v.y);
        atomicAdd(dst + 4 * e + 2, v.z);
        atomicAdd(dst + 4 * e + 3, v.w);
    }
    if (lane == 0) atomicAdd(&g_counts[k], 1.0f);
}

// ---------------- EMA cluster sizes + total n ----------------
__global__ void newcs_kernel(const float* __restrict__ ema_cs) {
    __shared__ float red[1024];
    int t = threadIdx.x;  // 1024 threads
    float v = DECAY * ema_cs[t] + OMD * g_counts[t];
    g_newcs[t] = v;
    red[t] = v;
    __syncthreads();
    for (int s = 512; s > 0; s >>= 1) {
        if (t < s) red[t] += red[t + s];
        __syncthreads();
    }
    if (t == 0) g_ntot = red[0];
}

// ---------------- normalized codebook ----------------
__global__ void norm_kernel(const float* __restrict__ ema_w) {
    int k = blockIdx.x;
    int t = threadIdx.x;  // 128 threads
    float n = g_ntot;
    float cs = g_newcs[k];
    float smoothed = (cs + EPS_C) / (n + (float)KCB * EPS_C) * n;
    float inv = 1.0f / smoothed;
    const float4* w = (const float4*)(ema_w + (size_t)k * DIM);
    const float4* s = (const float4*)(g_sums + (size_t)k * DIM);
    float4* o = (float4*)(g_norm + (size_t)k * DIM);
    float4 wv = w[t], sv = s[t], ov;
    ov.x = (DECAY * wv.x + OMD * sv.x) * inv;
    ov.y = (DECAY * wv.y + OMD * sv.y) * inv;
    ov.z = (DECAY * wv.z + OMD * sv.z) * inv;
    ov.w = (DECAY * wv.w + OMD * sv.w) * inv;
    o[t] = ov;
}

// ---------------- gather + emit outputs ----------------
__global__ void out_kernel(const float* __restrict__ z,
                           float* __restrict__ idx_out,
                           float* __restrict__ q_out,
                           float* __restrict__ st_out) {
    int row = blockIdx.x;
    int t = threadIdx.x;  // 128 threads
    int k = g_idx[row];
    const float4* nr = (const float4*)(g_norm + (size_t)k * DIM);
    float4 qv = nr[t];
    if (q_out)
        ((float4*)(q_out + (size_t)row * DIM))[t] = qv;
    if (st_out) {
        const float4* zr = (const float4*)(z + (size_t)row * DIM);
        float4 zv = zr[t];
        float4 sv;
        sv.x = zv.x + (qv.x - zv.x);
        sv.y = zv.y + (qv.y - zv.y);
        sv.z = zv.z + (qv.z - zv.z);
        sv.w = zv.w + (qv.w - zv.w);
        ((float4*)(st_out + (size_t)row * DIM))[t] = sv;
    }
    if (idx_out && t == 0) idx_out[row] = (float)k;
}

// ---------------- host launcher ----------------
extern "C" void kernel_launch(void* const* d_in, const int* in_sizes, int n_in,
                              void* d_out, int out_size) {
    const float* z   = (const float*)d_in[0];
    const float* cb  = (const float*)d_in[1];
    const float* ecs = (const float*)d_in[2];
    const float* ew  = (const float*)d_in[3];
    float* out = (float*)d_out;

    static bool attr_set = false;
    if (!attr_set) {
        cudaFuncSetAttribute(gemm_kernel,
                             cudaFuncAttributeMaxDynamicSharedMemorySize,
                             GSM_SIZE);
        attr_set = true;
    }

    zero_kernel<<<512, 256>>>();
    c2_kernel<<<KCB, 128>>>(cb);
    z2_kernel<<<N_TOK, 128>>>(z);
    gemm_kernel<<<N_TOK / 128, 256, GSM_SIZE>>>();
    scan_rerank_kernel<<<N_TOK / 256, 256>>>(z, cb);
    scatter_kernel<<<(N_TOK * 32) / 256, 256>>>(z);
    newcs_kernel<<<1, 1024>>>(ecs);
    norm_kernel<<<KCB, 128>>>(ew);

    const long long N = N_TOK, D = DIM;
    const long long os = out_size;
    float *idxp = nullptr, *qp = nullptr, *stp = nullptr;
    if (os == N * (2 * D + 1)) {            // [idx, q, q_st]
        idxp = out; qp = out + N; stp = out + N + N * D;
    } else if (os == N * 2 * D) {           // [q, q_st]
        qp = out; stp = out + N * D;
    } else if (os == N * D) {               // [q]
        qp = out;
    } else if (os == N) {                   // [idx]
        idxp = out;
    } else {
        idxp = out;
        if (os >= N + N * D) qp = out + N;
        if (os >= N + 2 * N * D) stp = out + N + N * D;
    }
    out_kernel<<<N_TOK, 128>>>(z, idxp, qp, stp);
}

// round 17
// speedup vs baseline: 46.3416x; 1.0897x over previous
#include <cuda_runtime.h>
#include <cuda_bf16.h>
#include <mma.h>
#include <stdint.h>

using namespace nvcuda;

#define N_TOK 32768
#define DIM   512
#define KCB   1024

#define DECAY 0.99f
#define OMD   0.01f
#define EPS_C 1e-5f
#define MARGIN 0.15f   // candidate window; near-min spacing (Gumbel beta) ~0.22
#define SLOTS 16

// ---------------- scratch (no allocations allowed) ----------------
__device__ float g_c2[KCB];
__device__ float g_z2[N_TOK];
__device__ int   g_idx[N_TOK];
__device__ float g_counts[KCB];
__device__ float g_sums[KCB * DIM];
__device__ float g_newcs[KCB];
__device__ float g_ntot;
__device__ float g_norm[KCB * DIM];
__device__ __align__(16) __nv_bfloat16 g_zh[N_TOK * (size_t)DIM];
__device__ __align__(16) __nv_bfloat16 g_cbh[KCB * DIM];
__device__ float g_scores[(size_t)KCB * N_TOK];   // [code][row]

// ---------------- zero accumulators ----------------
__global__ void zero_kernel() {
    int t = blockIdx.x * blockDim.x + threadIdx.x;
    int stride = gridDim.x * blockDim.x;
    for (int i = t; i < KCB * DIM; i += stride) g_sums[i] = 0.0f;
    if (t < KCB) g_counts[t] = 0.0f;
}

// ---------------- c2/z2 + fused bf16 conversion ----------------
__global__ void c2_kernel(const float* __restrict__ cb) {
    int k = blockIdx.x, t = threadIdx.x;  // 128 threads
    float4 v = ((const float4*)(cb + (size_t)k * DIM))[t];
    union { __nv_bfloat162 h[2]; uint2 u; } cv;
    cv.h[0] = __floats2bfloat162_rn(v.x, v.y);
    cv.h[1] = __floats2bfloat162_rn(v.z, v.w);
    ((uint2*)(g_cbh + (size_t)k * DIM))[t] = cv.u;
    float s = v.x * v.x + v.y * v.y + v.z * v.z + v.w * v.w;
    #pragma unroll
    for (int o = 16; o > 0; o >>= 1) s += __shfl_down_sync(0xffffffffu, s, o);
    __shared__ float ws[4];
    if ((t & 31) == 0) ws[t >> 5] = s;
    __syncthreads();
    if (t == 0) g_c2[k] = ws[0] + ws[1] + ws[2] + ws[3];
}

__global__ void z2_kernel(const float* __restrict__ z) {
    int r = blockIdx.x, t = threadIdx.x;  // 128 threads
    float4 v = ((const float4*)(z + (size_t)r * DIM))[t];
    union { __nv_bfloat162 h[2]; uint2 u; } cv;
    cv.h[0] = __floats2bfloat162_rn(v.x, v.y);
    cv.h[1] = __floats2bfloat162_rn(v.z, v.w);
    ((uint2*)(g_zh + (size_t)r * DIM))[t] = cv.u;
    float s = v.x * v.x + v.y * v.y + v.z * v.z + v.w * v.w;
    #pragma unroll
    for (int o = 16; o > 0; o >>= 1) s += __shfl_down_sync(0xffffffffu, s, o);
    __shared__ float ws[4];
    if ((t & 31) == 0) ws[t >> 5] = s;
    __syncthreads();
    if (t == 0) g_z2[r] = ws[0] + ws[1] + ws[2] + ws[3];
}

// ---------------- HMMA (wmma bf16) candidate GEMM ----------------
// VERBATIM R11 kernel (measured 239us / tensor 23.7% three rounds running).
#define PAW 72     // A/B smem pitch in bf16 (64 data + 8 pad)
#define PCW 132    // C smem pitch in f32 (128 rows + 4 pad)
#define OFF_A 0
#define OFF_B 18432
#define OFF_C 36864
#define OFF_C2 104448
#define GSM_SIZE 104960

__global__ __launch_bounds__(256)
void gemm_kernel() {
    extern __shared__ __align__(16) unsigned char sm[];
    __nv_bfloat16* As = (__nv_bfloat16*)(sm + OFF_A);   // [128][PAW]
    __nv_bfloat16* Bs = (__nv_bfloat16*)(sm + OFF_B);   // [128][PAW]
    float* Cs  = (float*)(sm + OFF_C);                  // [128 codes][PCW]
    float* c2s = (float*)(sm + OFF_C2);                 // [128]

    const int tid = threadIdx.x;
    const int wid = tid >> 5;
    const int wr = wid & 3;    // row group: rows wr*32
    const int wc = wid >> 2;   // col group: codes wc*64
    const int rb = blockIdx.x * 128;

    wmma::fragment<wmma::matrix_a, 16, 16, 16, __nv_bfloat16, wmma::row_major> af[2];
    wmma::fragment<wmma::matrix_b, 16, 16, 16, __nv_bfloat16, wmma::col_major> bf[4];
    wmma::fragment<wmma::accumulator, 16, 16, 16, float> acc[2][4];

    for (int ch = 0; ch < 8; ch++) {
        if (tid < 128) c2s[tid] = g_c2[ch * 128 + tid];
        #pragma unroll
        for (int f = 0; f < 2; f++)
            #pragma unroll
            for (int g = 0; g < 4; g++)
                wmma::fill_fragment(acc[f][g], 0.0f);

        for (int slab = 0; slab < 8; slab++) {
            #pragma unroll
            for (int i = 0; i < 4; i++) {
                int idx = i * 256 + tid;           // 0..1023
                int r = idx >> 3, grp = idx & 7;
                *(uint4*)(As + r * PAW + grp * 8) =
                    *(const uint4*)(g_zh + (size_t)(rb + r) * DIM + slab * 64 + grp * 8);
            }
            #pragma unroll
            for (int i = 0; i < 4; i++) {
                int idx = i * 256 + tid;
                int n = idx >> 3, grp = idx & 7;
                *(uint4*)(Bs + n * PAW + grp * 8) =
                    *(const uint4*)(g_cbh + (size_t)(ch * 128 + n) * DIM + slab * 64 + grp * 8);
            }
            __syncthreads();

            #pragma unroll
            for (int ks = 0; ks < 4; ks++) {
                #pragma unroll
                for (int f = 0; f < 2; f++)
                    wmma::load_matrix_sync(af[f],
                        As + (wr * 32 + f * 16) * PAW + ks * 16, PAW);
                #pragma unroll
                for (int g = 0; g < 4; g++)
                    wmma::load_matrix_sync(bf[g],
                        Bs + (wc * 64 + g * 16) * PAW + ks * 16, PAW);
                #pragma unroll
                for (int f = 0; f < 2; f++)
                    #pragma unroll
                    for (int g = 0; g < 4; g++)
                        wmma::mma_sync(acc[f][g], af[f], bf[g], acc[f][g]);
            }
            __syncthreads();
        }

        // store acc col-major: element (row r, code c) -> Cs[c*PCW + r]
        #pragma unroll
        for (int f = 0; f < 2; f++)
            #pragma unroll
            for (int g = 0; g < 4; g++)
                wmma::store_matrix_sync(
                    Cs + (wc * 64 + g * 16) * PCW + wr * 32 + f * 16,
                    acc[f][g], PCW, wmma::mem_col_major);
        __syncthreads();

        // coalesced transposed write: score = c2 - 2*dot
        #pragma unroll
        for (int i = 0; i < 64; i++) {
            int idx = i * 256 + tid;
            int r = idx & 127;
            int c = idx >> 7;
            float dot = Cs[c * PCW + r];
            g_scores[(size_t)(ch * 128 + c) * N_TOK + rb + r] =
                fmaf(-2.0f, dot, c2s[c]);
        }
        __syncthreads();
    }
}

// ---------------- exact rescore of one candidate (reference-exact) -------
// Sequential ascending-d fp32 FMA chain; d2 = fl(fl(z2-2dot)+c2); callers
// process codes in ascending order with strict '<' => lowest-index tie-break.
__device__ __forceinline__ void exact_update(const float* __restrict__ zr,
                                             const float* __restrict__ cb,
                                             float z2v, int code,
                                             float& best, int& bi) {
    const float* cr = cb + (size_t)code * DIM;
    float dot = 0.0f;
    #pragma unroll 8
    for (int d = 0; d < DIM; d++) dot = fmaf(zr[d], cr[d], dot);
    float t = fmaf(-2.0f, dot, z2v);
    float sc = __fadd_rn(t, g_c2[code]);
    if (sc < best) { best = sc; bi = code; }
}

// ---------------- two-pass scan + exact fp32 rerank ----------------
// Block = 256 consecutive rows, thread owns one row (coalesced streams).
// PASS 1: branch-free min-reduce (batched loads, MLP~16).
// PASS 2: batched 8-load groups -> min8 -> rare collection tail (prob
//   ~2/128 per group). No branches between loads => ptxas front-batches.
//   Candidate slots in SMEM (dynamic indexing without local-mem traffic).
// Rerank: exact reference arithmetic, identical to R4/R7/R11.
__global__ __launch_bounds__(256)
void scan_rerank_kernel(const float* __restrict__ z, const float* __restrict__ cb) {
    __shared__ int s_cand[256][SLOTS];   // 16 KB
    const int tid = threadIdx.x;
    const int row = blockIdx.x * 256 + tid;
    const float* sp = g_scores + row;

    // pass 1: pure min, 4 chains
    float m0 = 3.4e38f, m1 = 3.4e38f, m2 = 3.4e38f, m3 = 3.4e38f;
    #pragma unroll 2
    for (int c = 0; c < KCB; c += 8) {
        m0 = fminf(m0, fminf(sp[(size_t)(c + 0) * N_TOK], sp[(size_t)(c + 4) * N_TOK]));
        m1 = fminf(m1, fminf(sp[(size_t)(c + 1) * N_TOK], sp[(size_t)(c + 5) * N_TOK]));
        m2 = fminf(m2, fminf(sp[(size_t)(c + 2) * N_TOK], sp[(size_t)(c + 6) * N_TOK]));
        m3 = fminf(m3, fminf(sp[(size_t)(c + 3) * N_TOK], sp[(size_t)(c + 7) * N_TOK]));
    }
    const float rm = fminf(fminf(m0, m1), fminf(m2, m3));
    const float thr = rm + MARGIN;   // FINAL threshold

    // pass 2: batched loads, rare collection tail
    int cnt = 0;
    #pragma unroll 2
    for (int c = 0; c < KCB; c += 8) {
        float v0 = sp[(size_t)(c + 0) * N_TOK];
        float v1 = sp[(size_t)(c + 1) * N_TOK];
        float v2 = sp[(size_t)(c + 2) * N_TOK];
        float v3 = sp[(size_t)(c + 3) * N_TOK];
        float v4 = sp[(size_t)(c + 4) * N_TOK];
        float v5 = sp[(size_t)(c + 5) * N_TOK];
        float v6 = sp[(size_t)(c + 6) * N_TOK];
        float v7 = sp[(size_t)(c + 7) * N_TOK];
        float m8 = fminf(fminf(fminf(v0, v1), fminf(v2, v3)),
                         fminf(fminf(v4, v5), fminf(v6, v7)));
        if (m8 <= thr) {   // rare (~2 of 128 groups per row)
            float vv[8] = {v0, v1, v2, v3, v4, v5, v6, v7};
            #pragma unroll
            for (int j = 0; j < 8; j++) {
                if (vv[j] <= thr) {
                    if (cnt < SLOTS) s_cand[tid][cnt] = c + j;
                    cnt++;
                }
            }
        }
    }

    const float z2v = g_z2[row];
    const float* zr = z + (size_t)row * DIM;
    float best = 3.4e38f;
    int bi = 0;
    if (cnt <= SLOTS) {
        for (int i = 0; i < cnt; i++)
            exact_update(zr, cb, z2v, s_cand[tid][i], best, bi);
    } else {
        // chunked fallback (prob ~1e-5/row): ascending code order preserved
        int c = 0;
        while (c < KCB) {
            int n = 0;
            while (c < KCB && n < SLOTS) {
                float sc = sp[(size_t)c * N_TOK];
                if (sc <= thr) s_cand[tid][n++] = c;
                c++;
            }
            for (int i = 0; i < n; i++)
                exact_update(zr, cb, z2v, s_cand[tid][i], best, bi);
        }
    }
    g_idx[row] = bi;
}

// ---------------- scatter: counts[k] += 1, sums[k] += z_n ----------------
__global__ void scatter_kernel(const float* __restrict__ z) {
    int g = blockIdx.x * blockDim.x + threadIdx.x;
    int row = g >> 5;
    int lane = g & 31;
    if (row >= N_TOK) return;
    int k = g_idx[row];
    const float4* zr = (const float4*)(z + (size_t)row * DIM);
    float* dst = g_sums + (size_t)k * DIM;
    #pragma unroll
    for (int i = 0; i < 4; i++) {
        int e = lane + i * 32;
        float4 v = zr[e];
        atomicAdd(dst + 4 * e + 0, v.x);
        atomicAdd(dst + 4 * e + 1, v.y);
        atomicAdd(dst + 4 * e + 2, v.z);
        atomicAdd(dst + 4 * e + 3, v.w);
    }
    if (lane == 0) atomicAdd(&g_counts[k], 1.0f);
}

// ---------------- EMA cluster sizes + total n ----------------
__global__ void newcs_kernel(const float* __restrict__ ema_cs) {
    __shared__ float red[1024];
    int t = threadIdx.x;  // 1024 threads
    float v = DECAY * ema_cs[t] + OMD * g_counts[t];
    g_newcs[t] = v;
    red[t] = v;
    __syncthreads();
    for (int s = 512; s > 0; s >>= 1) {
        if (t < s) red[t] += red[t + s];
        __syncthreads();
    }
    if (t == 0) g_ntot = red[0];
}

// ---------------- normalized codebook ----------------
__global__ void norm_kernel(const float* __restrict__ ema_w) {
    int k = blockIdx.x;
    int t = threadIdx.x;  // 128 threads
    float n = g_ntot;
    float cs = g_newcs[k];
    float smoothed = (cs + EPS_C) / (n + (float)KCB * EPS_C) * n;
    float inv = 1.0f / smoothed;
    const float4* w = (const float4*)(ema_w + (size_t)k * DIM);
    const float4* s = (const float4*)(g_sums + (size_t)k * DIM);
    float4* o = (float4*)(g_norm + (size_t)k * DIM);
    float4 wv = w[t], sv = s[t], ov;
    ov.x = (DECAY * wv.x + OMD * sv.x) * inv;
    ov.y = (DECAY * wv.y + OMD * sv.y) * inv;
    ov.z = (DECAY * wv.z + OMD * sv.z) * inv;
    ov.w = (DECAY * wv.w + OMD * sv.w) * inv;
    o[t] = ov;
}

// ---------------- gather + emit outputs ----------------
__global__ void out_kernel(const float* __restrict__ z,
                           float* __restrict__ idx_out,
                           float* __restrict__ q_out,
                           float* __restrict__ st_out) {
    int row = blockIdx.x;
    int t = threadIdx.x;  // 128 threads
    int k = g_idx[row];
    const float4* nr = (const float4*)(g_norm + (size_t)k * DIM);
    float4 qv = nr[t];
    if (q_out)
        ((float4*)(q_out + (size_t)row * DIM))[t] = qv;
    if (st_out) {
        const float4* zr = (const float4*)(z + (size_t)row * DIM);
        float4 zv = zr[t];
        float4 sv;
        sv.x = zv.x + (qv.x - zv.x);
        sv.y = zv.y + (qv.y - zv.y);
        sv.z = zv.z + (qv.z - zv.z);
        sv.w = zv.w + (qv.w - zv.w);
        ((float4*)(st_out + (size_t)row * DIM))[t] = sv;
    }
    if (idx_out && t == 0) idx_out[row] = (float)k;
}

// ---------------- host launcher ----------------
extern "C" void kernel_launch(void* const* d_in, const int* in_sizes, int n_in,
                              void* d_out, int out_size) {
    const float* z   = (const float*)d_in[0];
    const float* cb  = (const float*)d_in[1];
    const float* ecs = (const float*)d_in[2];
    const float* ew  = (const float*)d_in[3];
    float* out = (float*)d_out;

    static bool attr_set = false;
    if (!attr_set) {
        cudaFuncSetAttribute(gemm_kernel,
                             cudaFuncAttributeMaxDynamicSharedMemorySize,
                             GSM_SIZE);
        attr_set = true;
    }

    zero_kernel<<<512, 256>>>();
    c2_kernel<<<KCB, 128>>>(cb);
    z2_kernel<<<N_TOK, 128>>>(z);
    gemm_kernel<<<N_TOK / 128, 256, GSM_SIZE>>>();
    scan_rerank_kernel<<<N_TOK / 256, 256>>>(z, cb);
    scatter_kernel<<<(N_TOK * 32) / 256, 256>>>(z);
    newcs_kernel<<<1, 1024>>>(ecs);
    norm_kernel<<<KCB, 128>>>(ew);

    const long long N = N_TOK, D = DIM;
    const long long os = out_size;
    float *idxp = nullptr, *qp = nullptr, *stp = nullptr;
    if (os == N * (2 * D + 1)) {            // [idx, q, q_st]
        idxp = out; qp = out + N; stp = out + N + N * D;
    } else if (os == N * 2 * D) {           // [q, q_st]
        qp = out; stp = out + N * D;
    } else if (os == N * D) {               // [q]
        qp = out;
    } else if (os == N) {                   // [idx]
        idxp = out;
    } else {
        idxp = out;
        if (os >= N + N * D) qp = out + N;
        if (os >= N + 2 * N * D) stp = out + N + N * D;
    }
    out_kernel<<<N_TOK, 128>>>(z, idxp, qp, stp);
}